// round 1
// baseline (speedup 1.0000x reference)
#include <cuda_runtime.h>
#include <math.h>

// Problem shape (fixed by reference)
#define B_ 8
#define H_ 8
#define Q_ 1024
#define K_ 1024
#define D_ 64
#define BH_ 64
#define QSCALE 0.125f   // 1/sqrt(64)

// -------------------------------------------------------------------------
// Kernel A: fused score + masked softmax -> alpha
// score[bh,i,j] = sum_d q_s[bh,i,d] * (k[bh,j,d] + rpe_q[i,j,d]),  q_s = q/8
// One CTA per (bh, i).  blockIdx.x = bh (fastest) so the 64 bh-CTAs sharing
// rpe_q row i run concurrently -> rpe_q row served from L2 once per row.
// -------------------------------------------------------------------------
__global__ __launch_bounds__(256, 8)
void rpe_score_softmax(const float* __restrict__ q,
                       const float* __restrict__ k,
                       const int*   __restrict__ mask,
                       const float* __restrict__ rpe_q,
                       float*       __restrict__ alpha)
{
    const int bh  = blockIdx.x;
    const int i   = blockIdx.y;
    const int tid = threadIdx.x;

    __shared__ float s_q[D_];
    __shared__ float s_sc[K_];
    __shared__ float s_red[8];

    if (tid < D_)
        s_q[tid] = q[((size_t)bh * Q_ + i) * D_ + tid] * QSCALE;
    __syncthreads();

    const float4* k4  = (const float4*)(k     + (size_t)bh * K_ * D_);
    const float4* r4  = (const float4*)(rpe_q + (size_t)i  * K_ * D_);
    const float4* q4  = (const float4*)s_q;
    const int*    mrow = mask + (size_t)i * K_;

    float lmax = -INFINITY;
    for (int j = tid; j < K_; j += 256) {
        float s;
        if (mrow[j] == 0) {
            s = -INFINITY;
        } else {
            const float4* kr = k4 + (size_t)j * (D_ / 4);
            const float4* rr = r4 + (size_t)j * (D_ / 4);
            float acc = 0.f;
            #pragma unroll
            for (int d4 = 0; d4 < D_ / 4; ++d4) {
                float4 kv = kr[d4];
                float4 rv = rr[d4];
                float4 qv = q4[d4];
                acc = fmaf(qv.x, kv.x + rv.x, acc);
                acc = fmaf(qv.y, kv.y + rv.y, acc);
                acc = fmaf(qv.z, kv.z + rv.z, acc);
                acc = fmaf(qv.w, kv.w + rv.w, acc);
            }
            s = acc;
            lmax = fmaxf(lmax, s);
        }
        s_sc[j] = s;
    }

    // block-reduce max (256 threads = 8 warps)
    #pragma unroll
    for (int o = 16; o > 0; o >>= 1)
        lmax = fmaxf(lmax, __shfl_xor_sync(0xffffffffu, lmax, o));
    if ((tid & 31) == 0) s_red[tid >> 5] = lmax;
    __syncthreads();
    float rmax;
    {
        float v0 = (tid < 8) ? s_red[tid] : -INFINITY;
        #pragma unroll
        for (int o = 4; o > 0; o >>= 1)
            v0 = fmaxf(v0, __shfl_xor_sync(0xffffffffu, v0, o));
        if (tid == 0) s_red[0] = v0;
    }
    __syncthreads();
    rmax = s_red[0];
    __syncthreads();

    const bool any_valid = isfinite(rmax);

    // exp + sum
    float lsum = 0.f;
    if (any_valid) {
        for (int j = tid; j < K_; j += 256) {
            float s = s_sc[j];
            float e = (s == -INFINITY) ? 0.f : __expf(s - rmax);
            s_sc[j] = e;
            lsum += e;
        }
    }
    #pragma unroll
    for (int o = 16; o > 0; o >>= 1)
        lsum += __shfl_xor_sync(0xffffffffu, lsum, o);
    if ((tid & 31) == 0) s_red[tid >> 5] = lsum;
    __syncthreads();
    {
        float v0 = (tid < 8) ? s_red[tid] : 0.f;
        #pragma unroll
        for (int o = 4; o > 0; o >>= 1)
            v0 += __shfl_xor_sync(0xffffffffu, v0, o);
        if (tid == 0) s_red[0] = v0;
    }
    __syncthreads();
    const float rsum = s_red[0];
    const float inv  = (any_valid && rsum > 0.f) ? (1.f / rsum) : 0.f;

    float* arow = alpha + ((size_t)bh * Q_ + i) * K_;
    for (int j = tid; j < K_; j += 256)
        arow[j] = any_valid ? (s_sc[j] * inv) : 0.f;
}

// -------------------------------------------------------------------------
// Kernel B: context[bh,i,d] = sum_j alpha[bh,i,j] * (v[bh,j,d] + rpe_v[i,j,d])
// One CTA per (bh, i); 256 threads = 4 j-groups x 64 d-lanes.
// alpha==0 (masked) entries skipped; j uniform within a warp -> no divergence.
// -------------------------------------------------------------------------
__global__ __launch_bounds__(256, 8)
void rpe_context(const float* __restrict__ v,
                 const float* __restrict__ rpe_v,
                 const float* __restrict__ alpha,
                 float*       __restrict__ out)
{
    const int bh  = blockIdx.x;
    const int i   = blockIdx.y;
    const int tid = threadIdx.x;
    const int d   = tid & (D_ - 1);
    const int g   = tid >> 6;            // 0..3

    __shared__ float s_a[K_];
    __shared__ float s_part[4][D_];

    const float* arow = alpha + ((size_t)bh * Q_ + i) * K_;
    for (int j = tid; j < K_; j += 256)
        s_a[j] = arow[j];
    __syncthreads();

    const float* vb = v     + (size_t)bh * K_ * D_;
    const float* rb = rpe_v + (size_t)i  * K_ * D_;

    float acc = 0.f;
    for (int j = g; j < K_; j += 4) {
        float a = s_a[j];
        if (a != 0.f) {
            acc = fmaf(a, vb[(size_t)j * D_ + d] + rb[(size_t)j * D_ + d], acc);
        }
    }
    s_part[g][d] = acc;
    __syncthreads();

    if (tid < D_) {
        float r = s_part[0][tid] + s_part[1][tid] + s_part[2][tid] + s_part[3][tid];
        out[((size_t)bh * Q_ + i) * D_ + tid] = r;
    }
}

// -------------------------------------------------------------------------
// Launch: inputs in order q, k, v, mask, rpe_q, rpe_v.
// d_out = [context (BH*Q*D floats)] [alpha (BH*Q*K floats)]
// -------------------------------------------------------------------------
extern "C" void kernel_launch(void* const* d_in, const int* in_sizes, int n_in,
                              void* d_out, int out_size)
{
    const float* q     = (const float*)d_in[0];
    const float* k     = (const float*)d_in[1];
    const float* v     = (const float*)d_in[2];
    const int*   mask  = (const int*)  d_in[3];
    const float* rpe_q = (const float*)d_in[4];
    const float* rpe_v = (const float*)d_in[5];

    float* ctx   = (float*)d_out;
    float* alpha = ctx + (size_t)BH_ * Q_ * D_;

    dim3 grid(BH_, Q_);
    rpe_score_softmax<<<grid, 256>>>(q, k, mask, rpe_q, alpha);
    rpe_context<<<grid, 256>>>(v, rpe_v, alpha, ctx);
}

// round 2
// speedup vs baseline: 11.0199x; 11.0199x over previous
#include <cuda_runtime.h>
#include <math.h>

#define QN 1024
#define KN 1024
#define DN 64
#define BHN 64
#define TS 64
#define QSCALE 0.125f

// q packed as [i][bh][d], pre-scaled by 1/sqrt(D)
__device__ float g_qp[(size_t)QN * BHN * DN];

// ---------------------------------------------------------------------------
// Swizzled transposed tile: T[64][64], element (r,c) stored at
//   r*64 + 4*(((c>>2) ^ (r>>2)) & 15) + (c&3)
// -> float4 reads along c are conflict-free; scalar transpose stores are 2-way.
// ---------------------------------------------------------------------------
__device__ __forceinline__ float4 ld_sw(const float* t, int r, int q4) {
    return *(const float4*)(t + r * 64 + 4 * ((q4 ^ (r >> 2)) & 15));
}

// Load a 64x64 gmem tile (row stride rs floats), store TRANSPOSED+swizzled:
// dst T[c][r] = src[r][c] * scale
__device__ __forceinline__ void load_tr(float* dst, const float* src, int rs,
                                        float scale, int tid) {
#pragma unroll
    for (int p = 0; p < 4; ++p) {
        int idx = tid + p * 256;
        int r = idx >> 4;
        int c4 = idx & 15;
        float4 v = *(const float4*)(src + (size_t)r * rs + c4 * 4);
        int swz = ((r >> 2) ^ c4) & 15;
        float* b = dst + 4 * swz + (r & 3);
        b[(4 * c4 + 0) * 64] = v.x * scale;
        b[(4 * c4 + 1) * 64] = v.y * scale;
        b[(4 * c4 + 2) * 64] = v.z * scale;
        b[(4 * c4 + 3) * 64] = v.w * scale;
    }
}

// Natural-layout 64x64 tile, stride 68 (padded)
__device__ __forceinline__ void load_nt(float* dst, const float* src, int rs,
                                        int tid) {
#pragma unroll
    for (int p = 0; p < 4; ++p) {
        int idx = tid + p * 256;
        int r = idx >> 4, c4 = idx & 15;
        float4 v = *(const float4*)(src + (size_t)r * rs + c4 * 4);
        *(float4*)(dst + r * 68 + c4 * 4) = v;
    }
}

#define FMA16(a, b, acc)                                                      \
    acc[0][0] = fmaf(a.x, b.x, acc[0][0]);                                    \
    acc[0][1] = fmaf(a.x, b.y, acc[0][1]);                                    \
    acc[0][2] = fmaf(a.x, b.z, acc[0][2]);                                    \
    acc[0][3] = fmaf(a.x, b.w, acc[0][3]);                                    \
    acc[1][0] = fmaf(a.y, b.x, acc[1][0]);                                    \
    acc[1][1] = fmaf(a.y, b.y, acc[1][1]);                                    \
    acc[1][2] = fmaf(a.y, b.z, acc[1][2]);                                    \
    acc[1][3] = fmaf(a.y, b.w, acc[1][3]);                                    \
    acc[2][0] = fmaf(a.z, b.x, acc[2][0]);                                    \
    acc[2][1] = fmaf(a.z, b.y, acc[2][1]);                                    \
    acc[2][2] = fmaf(a.z, b.z, acc[2][2]);                                    \
    acc[2][3] = fmaf(a.z, b.w, acc[2][3]);                                    \
    acc[3][0] = fmaf(a.w, b.x, acc[3][0]);                                    \
    acc[3][1] = fmaf(a.w, b.y, acc[3][1]);                                    \
    acc[3][2] = fmaf(a.w, b.z, acc[3][2]);                                    \
    acc[3][3] = fmaf(a.w, b.w, acc[3][3]);

// both operands transposed-swizzled: acc[ii][jj] += sum_r A[r][4ty+ii]*B[r][4tx+jj]
__device__ __forceinline__ void mma_tt(const float* A, const float* B,
                                       float acc[4][4], int tx, int ty) {
#pragma unroll
    for (int r = 0; r < 64; ++r) {
        float4 a = ld_sw(A, r, ty);
        float4 b = ld_sw(B, r, tx);
        FMA16(a, b, acc)
    }
}

// A transposed-swizzled, B natural (stride 68)
__device__ __forceinline__ void mma_tn(const float* A, const float* B,
                                       float acc[4][4], int tx, int ty) {
#pragma unroll
    for (int r = 0; r < 64; ++r) {
        float4 a = ld_sw(A, r, ty);
        float4 b = *(const float4*)(B + r * 68 + tx * 4);
        FMA16(a, b, acc)
    }
}

// ---------------------------------------------------------------------------
// pack q -> [i][bh][d], scaled
// ---------------------------------------------------------------------------
__global__ __launch_bounds__(256) void k_pack(const float* __restrict__ q) {
    int i = blockIdx.x, tid = threadIdx.x;
#pragma unroll
    for (int p = 0; p < 4; ++p) {
        int idx = tid + p * 256;
        int bh = idx >> 4, c4 = idx & 15;
        float4 v = *(const float4*)(q + ((size_t)bh * QN + i) * DN + c4 * 4);
        v.x *= QSCALE; v.y *= QSCALE; v.z *= QSCALE; v.w *= QSCALE;
        *(float4*)(g_qp + (size_t)i * (BHN * DN) + bh * DN + c4 * 4) = v;
    }
}

// ---------------------------------------------------------------------------
// G1: score[bh,i,j] = q_s[bh,i,:].k[bh,j,:]   (causal tiles only)
// ---------------------------------------------------------------------------
__global__ __launch_bounds__(256) void k_score_qk(const float* __restrict__ q,
                                                  const float* __restrict__ kk,
                                                  float* __restrict__ alpha) {
    int tj = blockIdx.x, ti = blockIdx.y, bh = blockIdx.z;
    if (tj > ti) return;
    __shared__ alignas(16) float As[TS * TS];
    __shared__ alignas(16) float Bs[TS * TS];
    int tid = threadIdx.x, tx = tid & 15, ty = tid >> 4;
    load_tr(As, q + ((size_t)bh * QN + ti * TS) * DN, DN, QSCALE, tid);
    load_tr(Bs, kk + ((size_t)bh * KN + tj * TS) * DN, DN, 1.f, tid);
    __syncthreads();
    float acc[4][4] = {};
    mma_tt(As, Bs, acc, tx, ty);
    float* C = alpha + ((size_t)bh * QN + ti * TS + ty * 4) * KN + tj * TS + tx * 4;
#pragma unroll
    for (int ii = 0; ii < 4; ++ii)
        *(float4*)(C + (size_t)ii * KN) =
            make_float4(acc[ii][0], acc[ii][1], acc[ii][2], acc[ii][3]);
}

// ---------------------------------------------------------------------------
// G2: score[bh,i,j] += q_s[bh,i,:].rpe_q[i,j,:]  — per-i GEMM over bh
//     (rpe_q read ONCE from DRAM, reused across all 64 bh via smem)
// ---------------------------------------------------------------------------
__global__ __launch_bounds__(256) void k_score_rpe(const float* __restrict__ rq,
                                                   float* __restrict__ alpha) {
    int tj = blockIdx.x, i = blockIdx.y;
    if (tj * TS > i) return;
    __shared__ alignas(16) float As[TS * TS];
    __shared__ alignas(16) float Bs[TS * TS];
    int tid = threadIdx.x, tx = tid & 15, ty = tid >> 4;
    load_tr(As, g_qp + (size_t)i * (BHN * DN), DN, 1.f, tid);
    load_tr(Bs, rq + ((size_t)i * KN + tj * TS) * DN, DN, 1.f, tid);
    __syncthreads();
    float acc[4][4] = {};
    mma_tt(As, Bs, acc, tx, ty);
#pragma unroll
    for (int ii = 0; ii < 4; ++ii) {
        int bh = ty * 4 + ii;
        float4* C = (float4*)(alpha + ((size_t)bh * QN + i) * KN + tj * TS + tx * 4);
        float4 o = *C;
        o.x += acc[ii][0]; o.y += acc[ii][1];
        o.z += acc[ii][2]; o.w += acc[ii][3];
        *C = o;
    }
}

// ---------------------------------------------------------------------------
// masked softmax, in place over alpha rows. K=1024 = 256 threads x float4.
// ---------------------------------------------------------------------------
__global__ __launch_bounds__(256) void k_softmax(const int* __restrict__ mask,
                                                 float* __restrict__ alpha) {
    int bh = blockIdx.x, i = blockIdx.y;
    int tid = threadIdx.x;
    float4* row = (float4*)(alpha + ((size_t)bh * QN + i) * KN);
    const int4* m4 = (const int4*)(mask + (size_t)i * KN);
    __shared__ float red[8];
    int4 m = m4[tid];
    float4 s = row[tid];
    float s0 = m.x ? s.x : -INFINITY;
    float s1 = m.y ? s.y : -INFINITY;
    float s2 = m.z ? s.z : -INFINITY;
    float s3 = m.w ? s.w : -INFINITY;
    float vmax = fmaxf(fmaxf(s0, s1), fmaxf(s2, s3));
#pragma unroll
    for (int o = 16; o > 0; o >>= 1)
        vmax = fmaxf(vmax, __shfl_xor_sync(0xffffffffu, vmax, o));
    if ((tid & 31) == 0) red[tid >> 5] = vmax;
    __syncthreads();
    if (tid < 32) {
        float w = (tid < 8) ? red[tid] : -INFINITY;
#pragma unroll
        for (int o = 4; o > 0; o >>= 1)
            w = fmaxf(w, __shfl_xor_sync(0xffffffffu, w, o));
        if (tid == 0) red[0] = w;
    }
    __syncthreads();
    float rmax = red[0];
    __syncthreads();
    bool any = isfinite(rmax);
    float e0 = 0.f, e1 = 0.f, e2 = 0.f, e3 = 0.f;
    if (any) {
        e0 = __expf(s0 - rmax);
        e1 = __expf(s1 - rmax);
        e2 = __expf(s2 - rmax);
        e3 = __expf(s3 - rmax);
    }
    float t = e0 + e1 + e2 + e3;
#pragma unroll
    for (int o = 16; o > 0; o >>= 1) t += __shfl_xor_sync(0xffffffffu, t, o);
    if ((tid & 31) == 0) red[tid >> 5] = t;
    __syncthreads();
    if (tid < 32) {
        float w = (tid < 8) ? red[tid] : 0.f;
#pragma unroll
        for (int o = 4; o > 0; o >>= 1) w += __shfl_xor_sync(0xffffffffu, w, o);
        if (tid == 0) red[0] = w;
    }
    __syncthreads();
    float rsum = red[0];
    float inv = (any && rsum > 0.f) ? (1.f / rsum) : 0.f;
    row[tid] = make_float4(e0 * inv, e1 * inv, e2 * inv, e3 * inv);
}

// ---------------------------------------------------------------------------
// G3: ctx[bh,i,d] = sum_j alpha[bh,i,j] * v[bh,j,d]   (causal K-loop)
// ---------------------------------------------------------------------------
__global__ __launch_bounds__(256) void k_ctx_v(const float* __restrict__ alpha,
                                               const float* __restrict__ v,
                                               float* __restrict__ ctx) {
    int ti = blockIdx.x, bh = blockIdx.y;
    __shared__ alignas(16) float As[TS * TS];
    __shared__ alignas(16) float Bs[TS * 68];
    int tid = threadIdx.x, tx = tid & 15, ty = tid >> 4;
    float acc[4][4] = {};
    for (int jt = 0; jt <= ti; ++jt) {
        load_tr(As, alpha + ((size_t)bh * QN + ti * TS) * KN + jt * TS, KN, 1.f, tid);
        load_nt(Bs, v + ((size_t)bh * KN + jt * TS) * DN, DN, tid);
        __syncthreads();
        mma_tn(As, Bs, acc, tx, ty);
        __syncthreads();
    }
    float* C = ctx + ((size_t)bh * QN + ti * TS + ty * 4) * DN + tx * 4;
#pragma unroll
    for (int ii = 0; ii < 4; ++ii)
        *(float4*)(C + ii * DN) =
            make_float4(acc[ii][0], acc[ii][1], acc[ii][2], acc[ii][3]);
}

// ---------------------------------------------------------------------------
// G4: ctx[bh,i,d] += sum_j alpha[bh,i,j] * rpe_v[i,j,d]  — per-i GEMM over bh
//     (rpe_v read ONCE from DRAM). i reversed so big CTAs launch first.
// ---------------------------------------------------------------------------
__global__ __launch_bounds__(256) void k_ctx_rpe(const float* __restrict__ alpha,
                                                 const float* __restrict__ rv,
                                                 float* __restrict__ ctx) {
    int i = (QN - 1) - blockIdx.x;
    int nt = (i >> 6) + 1;
    __shared__ alignas(16) float As[TS * TS];
    __shared__ alignas(16) float Bs[TS * 68];
    int tid = threadIdx.x, tx = tid & 15, ty = tid >> 4;
    float acc[4][4] = {};
    for (int jt = 0; jt < nt; ++jt) {
        load_tr(As, alpha + (size_t)i * KN + jt * TS, QN * KN, 1.f, tid);
        load_nt(Bs, rv + ((size_t)i * KN + jt * TS) * DN, DN, tid);
        __syncthreads();
        mma_tn(As, Bs, acc, tx, ty);
        __syncthreads();
    }
#pragma unroll
    for (int ii = 0; ii < 4; ++ii) {
        int bh = ty * 4 + ii;
        float4* C = (float4*)(ctx + ((size_t)bh * QN + i) * DN + tx * 4);
        float4 o = *C;
        o.x += acc[ii][0]; o.y += acc[ii][1];
        o.z += acc[ii][2]; o.w += acc[ii][3];
        *C = o;
    }
}

// ---------------------------------------------------------------------------
extern "C" void kernel_launch(void* const* d_in, const int* in_sizes, int n_in,
                              void* d_out, int out_size) {
    const float* q    = (const float*)d_in[0];
    const float* kk   = (const float*)d_in[1];
    const float* v    = (const float*)d_in[2];
    const int*   mask = (const int*)  d_in[3];
    const float* rq   = (const float*)d_in[4];
    const float* rv   = (const float*)d_in[5];

    float* ctx   = (float*)d_out;
    float* alpha = ctx + (size_t)BHN * QN * DN;

    k_pack<<<QN, 256>>>(q);
    k_score_qk<<<dim3(16, 16, BHN), 256>>>(q, kk, alpha);
    k_score_rpe<<<dim3(16, QN), 256>>>(rq, alpha);
    k_softmax<<<dim3(BHN, QN), 256>>>(mask, alpha);
    k_ctx_v<<<dim3(16, BHN), 256>>>(alpha, v, ctx);
    k_ctx_rpe<<<QN, 256>>>(alpha, rv, ctx);
}

// round 6
// speedup vs baseline: 11.8560x; 1.0759x over previous
#include <cuda_runtime.h>
#include <math.h>

#define QN 1024
#define KN 1024
#define DN 64
#define BHN 64
#define QSCALE 0.125f

#define LA 36   // A-type tile row stride: [p][k] (p = m or n), addr = p*36+c -> banks 4p+c all distinct
#define LB 72   // B-natural tile row stride: [k][n], addr = k*72+n -> banks 8k+n all distinct

// q packed as [i][bh][d], pre-scaled
__device__ float g_qp[(size_t)QN * BHN * DN];

// ---------------------------------------------------------------------------
__device__ __forceinline__ unsigned cvt_tf32(float x) {
    unsigned u;
    asm("cvt.rna.tf32.f32 %0, %1;" : "=r"(u) : "f"(x));
    return u;
}

// split x into hi (tf32) and lo (tf32 of residual)
__device__ __forceinline__ void split2(float x, float& h, float& l) {
    unsigned uh = cvt_tf32(x);
    h = __uint_as_float(uh);
    l = __uint_as_float(cvt_tf32(x - h));
}

// Fill A-type tile [64 rows][32 cols], stride LA, hi/lo split.
__device__ __forceinline__ void fillA(float* hi, float* lo, const float* src,
                                      int rs, float scale, int tid) {
#pragma unroll
    for (int ph = 0; ph < 2; ++ph) {
        int idx = tid + ph * 256;
        int p = idx >> 3, c4 = idx & 7;
        float4 v = *(const float4*)(src + (size_t)p * rs + c4 * 4);
        float4 h, l;
        split2(v.x * scale, h.x, l.x);
        split2(v.y * scale, h.y, l.y);
        split2(v.z * scale, h.z, l.z);
        split2(v.w * scale, h.w, l.w);
        *(float4*)(hi + p * LA + c4 * 4) = h;
        *(float4*)(lo + p * LA + c4 * 4) = l;
    }
}

// Fill B-natural tile [32 rows(k)][64 cols(n)], stride LB, hi/lo split.
__device__ __forceinline__ void fillB(float* hi, float* lo, const float* src,
                                      int rs, int tid) {
#pragma unroll
    for (int ph = 0; ph < 2; ++ph) {
        int idx = tid + ph * 256;
        int p = idx >> 4, c4 = idx & 15;
        float4 v = *(const float4*)(src + (size_t)p * rs + c4 * 4);
        float4 h, l;
        split2(v.x, h.x, l.x);
        split2(v.y, h.y, l.y);
        split2(v.z, h.z, l.z);
        split2(v.w, h.w, l.w);
        *(float4*)(hi + p * LB + c4 * 4) = h;
        *(float4*)(lo + p * LB + c4 * 4) = l;
    }
}

// ---------------------------------------------------------------------------
__device__ __forceinline__ void ldAfrag(const float* t, int m0, int k0,
                                        int lane, unsigned a[4]) {
    const float* b = t + (m0 + (lane >> 2)) * LA + k0 + (lane & 3);
    a[0] = __float_as_uint(b[0]);
    a[1] = __float_as_uint(b[8 * LA]);
    a[2] = __float_as_uint(b[4]);
    a[3] = __float_as_uint(b[8 * LA + 4]);
}
__device__ __forceinline__ void ldBnk(const float* t, int n0, int k0,
                                      int lane, unsigned b2[2]) {
    const float* b = t + (n0 + (lane >> 2)) * LA + k0 + (lane & 3);
    b2[0] = __float_as_uint(b[0]);
    b2[1] = __float_as_uint(b[4]);
}
__device__ __forceinline__ void ldBkn(const float* t, int n0, int k0,
                                      int lane, unsigned b2[2]) {
    const float* b = t + (k0 + (lane & 3)) * LB + n0 + (lane >> 2);
    b2[0] = __float_as_uint(b[0]);
    b2[1] = __float_as_uint(b[4 * LB]);
}

__device__ __forceinline__ void mma8(float d[4], const unsigned a[4],
                                     const unsigned b[2]) {
    asm volatile(
        "mma.sync.aligned.m16n8k8.row.col.f32.tf32.tf32.f32 "
        "{%0,%1,%2,%3},{%4,%5,%6,%7},{%8,%9},{%0,%1,%2,%3};"
        : "+f"(d[0]), "+f"(d[1]), "+f"(d[2]), "+f"(d[3])
        : "r"(a[0]), "r"(a[1]), "r"(a[2]), "r"(a[3]), "r"(b[0]), "r"(b[1]));
}

// 3xtf32 over one k32 chunk; B in [n][k] (stride LA) layout
__device__ __forceinline__ void gemm_nk(const float* Ah, const float* Al,
                                        const float* Bh, const float* Bl,
                                        float acc[4][4], int wm, int wn,
                                        int lane) {
    int m0 = wm * 16, n0 = wn * 32;
#pragma unroll
    for (int k0 = 0; k0 < 32; k0 += 8) {
        unsigned ah[4], al[4];
        ldAfrag(Ah, m0, k0, lane, ah);
        ldAfrag(Al, m0, k0, lane, al);
#pragma unroll
        for (int g = 0; g < 4; ++g) {
            unsigned bh2[2], bl2[2];
            ldBnk(Bh, n0 + 8 * g, k0, lane, bh2);
            ldBnk(Bl, n0 + 8 * g, k0, lane, bl2);
            mma8(acc[g], ah, bh2);
            mma8(acc[g], ah, bl2);
            mma8(acc[g], al, bh2);
        }
    }
}

// 3xtf32 over one k32 chunk; B natural [k][n] (stride LB)
__device__ __forceinline__ void gemm_kn(const float* Ah, const float* Al,
                                        const float* Bh, const float* Bl,
                                        float acc[4][4], int wm, int wn,
                                        int lane) {
    int m0 = wm * 16, n0 = wn * 32;
#pragma unroll
    for (int k0 = 0; k0 < 32; k0 += 8) {
        unsigned ah[4], al[4];
        ldAfrag(Ah, m0, k0, lane, ah);
        ldAfrag(Al, m0, k0, lane, al);
#pragma unroll
        for (int g = 0; g < 4; ++g) {
            unsigned bh2[2], bl2[2];
            ldBkn(Bh, n0 + 8 * g, k0, lane, bh2);
            ldBkn(Bl, n0 + 8 * g, k0, lane, bl2);
            mma8(acc[g], ah, bh2);
            mma8(acc[g], ah, bl2);
            mma8(acc[g], al, bh2);
        }
    }
}

// ---------------------------------------------------------------------------
__global__ __launch_bounds__(256) void k_pack(const float* __restrict__ q) {
    int i = blockIdx.x, tid = threadIdx.x;
#pragma unroll
    for (int p = 0; p < 4; ++p) {
        int idx = tid + p * 256;
        int bh = idx >> 4, c4 = idx & 15;
        float4 v = *(const float4*)(q + ((size_t)bh * QN + i) * DN + c4 * 4);
        v.x *= QSCALE; v.y *= QSCALE; v.z *= QSCALE; v.w *= QSCALE;
        *(float4*)(g_qp + (size_t)i * (BHN * DN) + bh * DN + c4 * 4) = v;
    }
}

// ---------------------------------------------------------------------------
// G1: score[bh,i,j] = q_s . k  (causal tiles)
// ---------------------------------------------------------------------------
__global__ __launch_bounds__(256) void k_score_qk(const float* __restrict__ q,
                                                  const float* __restrict__ kk,
                                                  float* __restrict__ alpha) {
    int tj = blockIdx.x, ti = blockIdx.y, bh = blockIdx.z;
    if (tj > ti) return;
    __shared__ alignas(16) float Ah[64 * LA], Al[64 * LA];
    __shared__ alignas(16) float Bh[64 * LA], Bl[64 * LA];
    int tid = threadIdx.x, lane = tid & 31, w = tid >> 5;
    int wm = w & 3, wn = w >> 2;
    float acc[4][4] = {};
#pragma unroll
    for (int kc = 0; kc < 2; ++kc) {
        fillA(Ah, Al, q + ((size_t)bh * QN + ti * 64) * DN + kc * 32, DN, QSCALE, tid);
        fillA(Bh, Bl, kk + ((size_t)bh * KN + tj * 64) * DN + kc * 32, DN, 1.f, tid);
        __syncthreads();
        gemm_nk(Ah, Al, Bh, Bl, acc, wm, wn, lane);
        __syncthreads();
    }
    int r0 = ti * 64 + wm * 16 + (lane >> 2);
    int c0 = tj * 64 + wn * 32 + 2 * (lane & 3);
    float* base = alpha + (size_t)bh * QN * KN;
#pragma unroll
    for (int g = 0; g < 4; ++g) {
        *(float2*)(base + (size_t)r0 * KN + c0 + 8 * g) = make_float2(acc[g][0], acc[g][1]);
        *(float2*)(base + (size_t)(r0 + 8) * KN + c0 + 8 * g) = make_float2(acc[g][2], acc[g][3]);
    }
}

// ---------------------------------------------------------------------------
// G2: score[bh,i,j] += q_s . rpe_q[i,j,:]  (per-i GEMM over bh; rpe read once)
// ---------------------------------------------------------------------------
__global__ __launch_bounds__(256) void k_score_rpe(const float* __restrict__ rq,
                                                   float* __restrict__ alpha) {
    int tj = blockIdx.x, i = blockIdx.y;
    if (tj * 64 > i) return;
    __shared__ alignas(16) float Ah[64 * LA], Al[64 * LA];
    __shared__ alignas(16) float Bh[64 * LA], Bl[64 * LA];
    int tid = threadIdx.x, lane = tid & 31, w = tid >> 5;
    int wm = w & 3, wn = w >> 2;
    float acc[4][4] = {};
#pragma unroll
    for (int kc = 0; kc < 2; ++kc) {
        fillA(Ah, Al, g_qp + (size_t)i * (BHN * DN) + kc * 32, DN, 1.f, tid);
        fillA(Bh, Bl, rq + ((size_t)i * KN + tj * 64) * DN + kc * 32, DN, 1.f, tid);
        __syncthreads();
        gemm_nk(Ah, Al, Bh, Bl, acc, wm, wn, lane);
        __syncthreads();
    }
    int bh0 = wm * 16 + (lane >> 2);
    int j0 = tj * 64 + wn * 32 + 2 * (lane & 3);
#pragma unroll
    for (int g = 0; g < 4; ++g) {
        float2* p0 = (float2*)(alpha + ((size_t)bh0 * QN + i) * KN + j0 + 8 * g);
        float2* p1 = (float2*)(alpha + ((size_t)(bh0 + 8) * QN + i) * KN + j0 + 8 * g);
        float2 v0 = *p0, v1 = *p1;
        v0.x += acc[g][0]; v0.y += acc[g][1];
        v1.x += acc[g][2]; v1.y += acc[g][3];
        *p0 = v0; *p1 = v1;
    }
}

// ---------------------------------------------------------------------------
// masked softmax, in place
// ---------------------------------------------------------------------------
__global__ __launch_bounds__(256) void k_softmax(const int* __restrict__ mask,
                                                 float* __restrict__ alpha) {
    int bh = blockIdx.x, i = blockIdx.y;
    int tid = threadIdx.x;
    float4* row = (float4*)(alpha + ((size_t)bh * QN + i) * KN);
    const int4* m4 = (const int4*)(mask + (size_t)i * KN);
    __shared__ float red[8];
    int4 m = m4[tid];
    float4 s = row[tid];
    float s0 = m.x ? s.x : -INFINITY;
    float s1 = m.y ? s.y : -INFINITY;
    float s2 = m.z ? s.z : -INFINITY;
    float s3 = m.w ? s.w : -INFINITY;
    float vmax = fmaxf(fmaxf(s0, s1), fmaxf(s2, s3));
#pragma unroll
    for (int o = 16; o > 0; o >>= 1)
        vmax = fmaxf(vmax, __shfl_xor_sync(0xffffffffu, vmax, o));
    if ((tid & 31) == 0) red[tid >> 5] = vmax;
    __syncthreads();
    if (tid < 32) {
        float w = (tid < 8) ? red[tid] : -INFINITY;
#pragma unroll
        for (int o = 4; o > 0; o >>= 1)
            w = fmaxf(w, __shfl_xor_sync(0xffffffffu, w, o));
        if (tid == 0) red[0] = w;
    }
    __syncthreads();
    float rmax = red[0];
    __syncthreads();
    bool any = isfinite(rmax);
    float e0 = 0.f, e1 = 0.f, e2 = 0.f, e3 = 0.f;
    if (any) {
        e0 = __expf(s0 - rmax);
        e1 = __expf(s1 - rmax);
        e2 = __expf(s2 - rmax);
        e3 = __expf(s3 - rmax);
    }
    float t = e0 + e1 + e2 + e3;
#pragma unroll
    for (int o = 16; o > 0; o >>= 1) t += __shfl_xor_sync(0xffffffffu, t, o);
    if ((tid & 31) == 0) red[tid >> 5] = t;
    __syncthreads();
    if (tid < 32) {
        float w = (tid < 8) ? red[tid] : 0.f;
#pragma unroll
        for (int o = 4; o > 0; o >>= 1) w += __shfl_xor_sync(0xffffffffu, w, o);
        if (tid == 0) red[0] = w;
    }
    __syncthreads();
    float rsum = red[0];
    float inv = (any && rsum > 0.f) ? (1.f / rsum) : 0.f;
    row[tid] = make_float4(e0 * inv, e1 * inv, e2 * inv, e3 * inv);
}

// ---------------------------------------------------------------------------
// G3: ctx = alpha @ v   (per (ti,bh); causal k-loop in 32-chunks)
// ---------------------------------------------------------------------------
__global__ __launch_bounds__(256) void k_ctx_v(const float* __restrict__ alpha,
                                               const float* __restrict__ v,
                                               float* __restrict__ ctx) {
    int ti = blockIdx.x, bh = blockIdx.y;
    __shared__ alignas(16) float Ah[64 * LA], Al[64 * LA];
    __shared__ alignas(16) float Bh[32 * LB], Bl[32 * LB];
    int tid = threadIdx.x, lane = tid & 31, w = tid >> 5;
    int wm = w & 3, wn = w >> 2;
    float acc[4][4] = {};
    int nch = (ti + 1) * 2;
    for (int kc = 0; kc < nch; ++kc) {
        fillA(Ah, Al, alpha + ((size_t)bh * QN + ti * 64) * KN + kc * 32, KN, 1.f, tid);
        fillB(Bh, Bl, v + ((size_t)bh * KN + kc * 32) * DN, DN, tid);
        __syncthreads();
        gemm_kn(Ah, Al, Bh, Bl, acc, wm, wn, lane);
        __syncthreads();
    }
    int r0 = ti * 64 + wm * 16 + (lane >> 2);
    int c0 = wn * 32 + 2 * (lane & 3);
    float* base = ctx + (size_t)bh * QN * DN;
#pragma unroll
    for (int g = 0; g < 4; ++g) {
        *(float2*)(base + (size_t)r0 * DN + c0 + 8 * g) = make_float2(acc[g][0], acc[g][1]);
        *(float2*)(base + (size_t)(r0 + 8) * DN + c0 + 8 * g) = make_float2(acc[g][2], acc[g][3]);
    }
}

// ---------------------------------------------------------------------------
// G4: ctx[bh,i,:] += sum_j alpha[bh,i,j] * rpe_v[i,j,:]  (per-i over bh)
// ---------------------------------------------------------------------------
__global__ __launch_bounds__(256) void k_ctx_rpe(const float* __restrict__ alpha,
                                                 const float* __restrict__ rv,
                                                 float* __restrict__ ctx) {
    int i = (QN - 1) - blockIdx.x;
    int nch = (i >> 5) + 1;
    __shared__ alignas(16) float Ah[64 * LA], Al[64 * LA];
    __shared__ alignas(16) float Bh[32 * LB], Bl[32 * LB];
    int tid = threadIdx.x, lane = tid & 31, w = tid >> 5;
    int wm = w & 3, wn = w >> 2;
    float acc[4][4] = {};
    for (int kc = 0; kc < nch; ++kc) {
        fillA(Ah, Al, alpha + (size_t)i * KN + kc * 32, QN * KN, 1.f, tid);
        fillB(Bh, Bl, rv + ((size_t)i * KN + kc * 32) * DN, DN, tid);
        __syncthreads();
        gemm_kn(Ah, Al, Bh, Bl, acc, wm, wn, lane);
        __syncthreads();
    }
    int bh0 = wm * 16 + (lane >> 2);
    int c0 = wn * 32 + 2 * (lane & 3);
#pragma unroll
    for (int g = 0; g < 4; ++g) {
        float2* p0 = (float2*)(ctx + ((size_t)bh0 * QN + i) * DN + c0 + 8 * g);
        float2* p1 = (float2*)(ctx + ((size_t)(bh0 + 8) * QN + i) * DN + c0 + 8 * g);
        float2 v0 = *p0, v1 = *p1;
        v0.x += acc[g][0]; v0.y += acc[g][1];
        v1.x += acc[g][2]; v1.y += acc[g][3];
        *p0 = v0; *p1 = v1;
    }
}

// ---------------------------------------------------------------------------
extern "C" void kernel_launch(void* const* d_in, const int* in_sizes, int n_in,
                              void* d_out, int out_size) {
    const float* q    = (const float*)d_in[0];
    const float* kk   = (const float*)d_in[1];
    const float* v    = (const float*)d_in[2];
    const int*   mask = (const int*)  d_in[3];
    const float* rq   = (const float*)d_in[4];
    const float* rv   = (const float*)d_in[5];

    float* ctx   = (float*)d_out;
    float* alpha = ctx + (size_t)BHN * QN * DN;

    k_pack<<<QN, 256>>>(q);
    k_score_qk<<<dim3(16, 16, BHN), 256>>>(q, kk, alpha);
    k_score_rpe<<<dim3(16, QN), 256>>>(rq, alpha);
    k_softmax<<<dim3(BHN, QN), 256>>>(mask, alpha);
    k_ctx_v<<<dim3(16, BHN), 256>>>(alpha, v, ctx);
    k_ctx_rpe<<<QN, 256>>>(alpha, rv, ctx);
}